// round 13
// baseline (speedup 1.0000x reference)
#include <cuda_runtime.h>
#include <math.h>
#include <float.h>
#include <stdint.h>

// Problem constants
#define Bv   8
#define Lv   4096
#define LP   4097          // L + 1 (bias token)
#define KDv  512
#define EDv  1024
#define DK   64            // KD / H
#define DV   128           // ED / H
#define BH   64            // B * H
#define KCHUNK   (LP * DK)
#define VCHUNK   (LP * DV)
#define KBATCH   (Lv * KDv)
#define VBATCH   (Lv * EDv)
#define NT   16
#define TILE 257           // ceil(4097 / 16)

// Scratch
__device__ float g_bsum[BH * NT];
__device__ float g_partial[BH * NT * DV];

// ---------------------------------------------------------------------------
// Fused kernel: 8 rows per warp-iteration. 4 half-warp K loads + 8 V loads
// all front-batched (MLP=12/thread), score shuffles overlap V latency.
// ---------------------------------------------------------------------------
__global__ void __launch_bounds__(256) k_fused(
        const float* __restrict__ keys,
        const float* __restrict__ k_bias,
        const float* __restrict__ values,
        const float* __restrict__ v_bias,
        const float* __restrict__ query,
        const float* __restrict__ sw,
        const float* __restrict__ sb) {
    __shared__ float4 sq[16];
    __shared__ float4 red[8][32];
    __shared__ float  shs[8];

    int tile = blockIdx.x;
    int bh   = blockIdx.y;
    int b = bh >> 3, h = bh & 7;
    int t    = threadIdx.x;
    int w    = t >> 5;
    int lane = t & 31;
    int half = lane >> 4;
    int li   = lane & 15;
    int c    = lane;

    if (t < 16) sq[t] = *((const float4*)(query + h * DK) + t);
    __syncthreads();

    const float* swh = sw + h * LP;
    const float* sbh = sb + h * LP;
    int kchunk = h * KCHUNK;
    int vchunk = h * VCHUNK;
    const float* kbat = keys   + (size_t)b * KBATCH;
    const float* vbat = values + (size_t)b * VBATCH;

    int j0 = tile * TILE;
    int j1 = min(j0 + TILE, LP);

    float4 acc  = make_float4(0.f, 0.f, 0.f, 0.f);
    float  esum = 0.0f;
    float4 qv   = sq[li];

    int j = j0 + w;
    // main loop: 8 rows (j .. j+56 step 8) per iteration
    for (; j + 56 < j1; j += 64) {
        // ---- front-batched K loads: 4 half-warp pairs ----
        float4 kv[4];
        int jk[4];
        #pragma unroll
        for (int i = 0; i < 4; i++) {
            jk[i] = j + i * 16 + half * 8;
            int fk = kchunk + jk[i] * DK + li * 4;
            const float* kp = (fk >= KBATCH) ? (k_bias + (fk - KBATCH))
                                             : (kbat + fk);
            kv[i] = __ldcs((const float4*)kp);
        }

        // ---- front-batched V loads: 8 rows ----
        float4 vv[8];
        #pragma unroll
        for (int i = 0; i < 8; i++) {
            int fv = vchunk + (j + i * 8) * DV;
            const float* rv = (fv >= VBATCH) ? (v_bias + (fv - VBATCH))
                                             : (vbat + fv);
            vv[i] = __ldcs((const float4*)(rv + c * 4));
        }

        // ---- scores for 8 rows (4 half-warp pairs) ----
        float e8[8];
        #pragma unroll
        for (int i = 0; i < 4; i++) {
            float s = kv[i].x * qv.x + kv[i].y * qv.y
                    + kv[i].z * qv.z + kv[i].w * qv.w;
            #pragma unroll
            for (int o = 8; o > 0; o >>= 1)
                s += __shfl_xor_sync(0xffffffffu, s, o);
            float e = expf(s * __ldg(swh + jk[i]) + __ldg(sbh + jk[i]));
            e8[2 * i]     = __shfl_sync(0xffffffffu, e, 0);
            e8[2 * i + 1] = __shfl_sync(0xffffffffu, e, 16);
        }

        #pragma unroll
        for (int i = 0; i < 8; i++) {
            acc.x += e8[i] * vv[i].x;
            acc.y += e8[i] * vv[i].y;
            acc.z += e8[i] * vv[i].z;
            acc.w += e8[i] * vv[i].w;
        }
        if (lane == 0)
            esum += ((e8[0] + e8[1]) + (e8[2] + e8[3]))
                  + ((e8[4] + e8[5]) + (e8[6] + e8[7]));
    }
    // tail: single rows
    for (; j < j1; j += 8) {
        int fk = kchunk + j * DK + li * 4;
        const float* kp = (fk >= KBATCH) ? (k_bias + (fk - KBATCH)) : (kbat + fk);
        float4 kv = __ldcs((const float4*)kp);
        float s = kv.x * qv.x + kv.y * qv.y + kv.z * qv.z + kv.w * qv.w;
        #pragma unroll
        for (int o = 8; o > 0; o >>= 1)
            s += __shfl_xor_sync(0xffffffffu, s, o);
        float e = expf(s * __ldg(swh + j) + __ldg(sbh + j));
        e = __shfl_sync(0xffffffffu, e, 0);

        int fA = vchunk + j * DV;
        const float* rA = (fA >= VBATCH) ? (v_bias + (fA - VBATCH)) : (vbat + fA);
        float4 vA = __ldcs((const float4*)(rA + c * 4));
        acc.x += e * vA.x;
        acc.y += e * vA.y;
        acc.z += e * vA.z;
        acc.w += e * vA.w;
        if (lane == 0) esum += e;
    }

    cudaTriggerProgrammaticLaunchCompletion();

    // cross-warp reduce
    red[w][c] = acc;
    if (lane == 0) shs[w] = esum;
    __syncthreads();
    if (w == 0) {
        float4 a = red[0][c];
        #pragma unroll
        for (int ww = 1; ww < 8; ww++) {
            float4 x = red[ww][c];
            a.x += x.x; a.y += x.y; a.z += x.z; a.w += x.w;
        }
        *(float4*)(g_partial + (bh * NT + tile) * DV + c * 4) = a;
        if (lane == 0) {
            float s = 0.0f;
            #pragma unroll
            for (int ww = 0; ww < 8; ww++) s += shs[ww];
            g_bsum[bh * NT + tile] = s;
        }
    }
}

// ---------------------------------------------------------------------------
// Kernel 2: S[bh] = sum of tile sums; reduce NT partials, /S, LayerNorm.
// PDL secondary.
// ---------------------------------------------------------------------------
__global__ void k_ln(const float* __restrict__ gamma,
                     const float* __restrict__ beta,
                     float* __restrict__ out) {
    __shared__ float sh_invS[8];
    __shared__ float sh_s[8];
    __shared__ float sh_q[8];
    int b = blockIdx.x;
    int t = threadIdx.x;
    int lane = t & 31, warp = t >> 5;

    int D  = t * 4;
    float4 gm = *(const float4*)(gamma + D);
    float4 bt = *(const float4*)(beta + D);

    cudaGridDependencySynchronize();

    {
        const float* bs = g_bsum + (b * 8 + warp) * NT;
        float s = (lane < NT) ? bs[lane] : 0.0f;
        #pragma unroll
        for (int o = 16; o > 0; o >>= 1)
            s += __shfl_xor_sync(0xffffffffu, s, o);
        if (lane == 0) sh_invS[warp] = 1.0f / s;
    }
    __syncthreads();

    int hh = t >> 5;
    int dd = D & 127;
    int bh = b * 8 + hh;

    const float* pp = g_partial + bh * (NT * DV) + dd;
    float4 a = make_float4(0.f, 0.f, 0.f, 0.f);
    #pragma unroll
    for (int k = 0; k < NT; k++) {
        float4 x = *(const float4*)(pp + k * DV);
        a.x += x.x; a.y += x.y; a.z += x.z; a.w += x.w;
    }
    float invS = sh_invS[hh];
    a.x *= invS; a.y *= invS; a.z *= invS; a.w *= invS;

    float s = a.x + a.y + a.z + a.w;
    float q = a.x * a.x + a.y * a.y + a.z * a.z + a.w * a.w;
    #pragma unroll
    for (int o = 16; o > 0; o >>= 1) {
        s += __shfl_xor_sync(0xffffffffu, s, o);
        q += __shfl_xor_sync(0xffffffffu, q, o);
    }
    if (lane == 0) { sh_s[warp] = s; sh_q[warp] = q; }
    __syncthreads();
    if (warp == 0 && lane < 8) {
        s = sh_s[lane];
        q = sh_q[lane];
        #pragma unroll
        for (int o = 4; o > 0; o >>= 1) {
            s += __shfl_xor_sync(0x000000ffu, s, o);
            q += __shfl_xor_sync(0x000000ffu, q, o);
        }
        if (lane == 0) { sh_s[0] = s; sh_q[0] = q; }
    }
    __syncthreads();
    float mean = sh_s[0] * (1.0f / EDv);
    float var  = sh_q[0] * (1.0f / EDv) - mean * mean;
    float inv  = rsqrtf(var + 1e-5f);

    float4 o4;
    o4.x = (a.x - mean) * inv * gm.x + bt.x;
    o4.y = (a.y - mean) * inv * gm.y + bt.y;
    o4.z = (a.z - mean) * inv * gm.z + bt.z;
    o4.w = (a.w - mean) * inv * gm.w + bt.w;
    *(float4*)(out + b * EDv + D) = o4;
}

// ---------------------------------------------------------------------------
// Launch
// ---------------------------------------------------------------------------
extern "C" void kernel_launch(void* const* d_in, const int* in_sizes, int n_in,
                              void* d_out, int out_size) {
    const float* keys   = (const float*)d_in[0];
    const float* values = (const float*)d_in[1];
    const float* query  = (const float*)d_in[2];
    const float* k_bias = (const float*)d_in[3];
    const float* v_bias = (const float*)d_in[4];
    const float* sw     = (const float*)d_in[5];
    const float* sb     = (const float*)d_in[6];
    const float* gamma  = (const float*)d_in[7];
    const float* beta   = (const float*)d_in[8];
    float* out = (float*)d_out;

    dim3 g1(NT, BH);
    k_fused<<<g1, 256>>>(keys, k_bias, values, v_bias, query, sw, sb);

    cudaLaunchConfig_t cfg = {};
    cfg.gridDim  = dim3(Bv);
    cfg.blockDim = dim3(256);
    cfg.dynamicSmemBytes = 0;
    cfg.stream = 0;
    cudaLaunchAttribute attrs[1];
    attrs[0].id = cudaLaunchAttributeProgrammaticStreamSerialization;
    attrs[0].val.programmaticStreamSerializationAllowed = 1;
    cfg.attrs = attrs;
    cfg.numAttrs = 1;
    cudaLaunchKernelEx(&cfg, k_ln, gamma, beta, out);
}

// round 14
// speedup vs baseline: 1.0189x; 1.0189x over previous
#include <cuda_runtime.h>
#include <math.h>
#include <float.h>
#include <stdint.h>

// Problem constants
#define Bv   8
#define Lv   4096
#define LP   4097          // L + 1 (bias token)
#define KDv  512
#define EDv  1024
#define DK   64            // KD / H
#define DV   128           // ED / H
#define BH   64            // B * H
#define KCHUNK   (LP * DK)
#define VCHUNK   (LP * DV)
#define KBATCH   (Lv * KDv)
#define VBATCH   (Lv * EDv)
#define NT   16
#define TILE 257           // ceil(4097 / 16)

// Scratch
__device__ float g_bsum[BH * NT];
__device__ float g_partial[BH * NT * DV];

// ---------------------------------------------------------------------------
// Fused kernel (R12 4-row body + K software prefetch):
//   s_j = dot64(Q[h],K[bh,j,:]); e_j = exp(s_j*w+b); acc += e_j * V[bh,j,:]
// 4 rows/iteration: 2 half-warp K pair loads (prefetched one iteration ahead)
// + 4 front-batched V row loads.
// ---------------------------------------------------------------------------
__global__ void __launch_bounds__(256) k_fused(
        const float* __restrict__ keys,
        const float* __restrict__ k_bias,
        const float* __restrict__ values,
        const float* __restrict__ v_bias,
        const float* __restrict__ query,
        const float* __restrict__ sw,
        const float* __restrict__ sb) {
    __shared__ float4 sq[16];
    __shared__ float4 red[8][32];
    __shared__ float  shs[8];

    int tile = blockIdx.x;
    int bh   = blockIdx.y;
    int b = bh >> 3, h = bh & 7;
    int t    = threadIdx.x;
    int w    = t >> 5;
    int lane = t & 31;
    int half = lane >> 4;
    int li   = lane & 15;
    int c    = lane;

    if (t < 16) sq[t] = *((const float4*)(query + h * DK) + t);
    __syncthreads();

    const float* swh = sw + h * LP;
    const float* sbh = sb + h * LP;
    int kchunk = h * KCHUNK;
    int vchunk = h * VCHUNK;
    const float* kbat = keys   + (size_t)b * KBATCH;
    const float* vbat = values + (size_t)b * VBATCH;

    int j0 = tile * TILE;
    int j1 = min(j0 + TILE, LP);

    float4 acc  = make_float4(0.f, 0.f, 0.f, 0.f);
    float  esum = 0.0f;
    float4 qv   = sq[li];

    // K pair loader: rows (jj + half*8), clamped for safe prefetch
    auto loadK = [&](int jj) -> float4 {
        int jk = min(jj + half * 8, LP - 1);
        int fk = kchunk + jk * DK + li * 4;
        const float* kp = (fk >= KBATCH) ? (k_bias + (fk - KBATCH))
                                         : (kbat + fk);
        return __ldcs((const float4*)kp);
    };

    int j = j0 + w;
    float4 kvA, kvB;
    if (j + 24 < j1) {                   // preload first iteration's K
        kvA = loadK(j);
        kvB = loadK(j + 16);
    }

    // main loop: 4 rows (j, j+8, j+16, j+24) per iteration
    for (; j + 24 < j1; j += 32) {
        // --- front-batched V loads: 4 rows ---
        int f0 = vchunk + j * DV;
        int f1 = f0 + 8 * DV, f2 = f0 + 16 * DV, f3 = f0 + 24 * DV;
        const float* r0 = (f0 >= VBATCH) ? (v_bias + (f0 - VBATCH)) : (vbat + f0);
        const float* r1 = (f1 >= VBATCH) ? (v_bias + (f1 - VBATCH)) : (vbat + f1);
        const float* r2 = (f2 >= VBATCH) ? (v_bias + (f2 - VBATCH)) : (vbat + f2);
        const float* r3 = (f3 >= VBATCH) ? (v_bias + (f3 - VBATCH)) : (vbat + f3);
        float4 v0 = __ldcs((const float4*)(r0 + c * 4));
        float4 v1 = __ldcs((const float4*)(r1 + c * 4));
        float4 v2 = __ldcs((const float4*)(r2 + c * 4));
        float4 v3 = __ldcs((const float4*)(r3 + c * 4));

        // --- prefetch next iteration's K pairs (discarded on last iter) ---
        float4 nkvA, nkvB;
        bool more = (j + 32 + 24 < j1);
        if (more) {
            nkvA = loadK(j + 32);
            nkvB = loadK(j + 48);
        }

        // --- scores for 4 rows from the current K registers ---
        int jkA = j + half * 8;
        int jkB = j + 16 + half * 8;
        float sA = kvA.x * qv.x + kvA.y * qv.y + kvA.z * qv.z + kvA.w * qv.w;
        float sB = kvB.x * qv.x + kvB.y * qv.y + kvB.z * qv.z + kvB.w * qv.w;
        #pragma unroll
        for (int o = 8; o > 0; o >>= 1) {
            sA += __shfl_xor_sync(0xffffffffu, sA, o);
            sB += __shfl_xor_sync(0xffffffffu, sB, o);
        }
        float eA2 = expf(sA * __ldg(swh + jkA) + __ldg(sbh + jkA));
        float eB2 = expf(sB * __ldg(swh + jkB) + __ldg(sbh + jkB));
        float e0 = __shfl_sync(0xffffffffu, eA2, 0);
        float e1 = __shfl_sync(0xffffffffu, eA2, 16);
        float e2 = __shfl_sync(0xffffffffu, eB2, 0);
        float e3 = __shfl_sync(0xffffffffu, eB2, 16);

        acc.x += e0 * v0.x + e1 * v1.x + e2 * v2.x + e3 * v3.x;
        acc.y += e0 * v0.y + e1 * v1.y + e2 * v2.y + e3 * v3.y;
        acc.z += e0 * v0.z + e1 * v1.z + e2 * v2.z + e3 * v3.z;
        acc.w += e0 * v0.w + e1 * v1.w + e2 * v2.w + e3 * v3.w;
        if (lane == 0) esum += (e0 + e1) + (e2 + e3);

        if (more) { kvA = nkvA; kvB = nkvB; }
    }
    // tail: single rows
    for (; j < j1; j += 8) {
        int fk = kchunk + j * DK + li * 4;
        const float* kp = (fk >= KBATCH) ? (k_bias + (fk - KBATCH)) : (kbat + fk);
        float4 kv = __ldcs((const float4*)kp);
        float s = kv.x * qv.x + kv.y * qv.y + kv.z * qv.z + kv.w * qv.w;
        #pragma unroll
        for (int o = 8; o > 0; o >>= 1)
            s += __shfl_xor_sync(0xffffffffu, s, o);
        float e = expf(s * __ldg(swh + j) + __ldg(sbh + j));
        e = __shfl_sync(0xffffffffu, e, 0);

        int fA = vchunk + j * DV;
        const float* rA = (fA >= VBATCH) ? (v_bias + (fA - VBATCH)) : (vbat + fA);
        float4 vA = __ldcs((const float4*)(rA + c * 4));
        acc.x += e * vA.x;
        acc.y += e * vA.y;
        acc.z += e * vA.z;
        acc.w += e * vA.w;
        if (lane == 0) esum += e;
    }

    cudaTriggerProgrammaticLaunchCompletion();

    // cross-warp reduce
    red[w][c] = acc;
    if (lane == 0) shs[w] = esum;
    __syncthreads();
    if (w == 0) {
        float4 a = red[0][c];
        #pragma unroll
        for (int ww = 1; ww < 8; ww++) {
            float4 x = red[ww][c];
            a.x += x.x; a.y += x.y; a.z += x.z; a.w += x.w;
        }
        *(float4*)(g_partial + (bh * NT + tile) * DV + c * 4) = a;
        if (lane == 0) {
            float s = 0.0f;
            #pragma unroll
            for (int ww = 0; ww < 8; ww++) s += shs[ww];
            g_bsum[bh * NT + tile] = s;
        }
    }
}

// ---------------------------------------------------------------------------
// Kernel 2: S[bh] = sum of tile sums; reduce NT partials, /S, LayerNorm.
// PDL secondary.
// ---------------------------------------------------------------------------
__global__ void k_ln(const float* __restrict__ gamma,
                     const float* __restrict__ beta,
                     float* __restrict__ out) {
    __shared__ float sh_invS[8];
    __shared__ float sh_s[8];
    __shared__ float sh_q[8];
    int b = blockIdx.x;
    int t = threadIdx.x;
    int lane = t & 31, warp = t >> 5;

    int D  = t * 4;
    float4 gm = *(const float4*)(gamma + D);
    float4 bt = *(const float4*)(beta + D);

    cudaGridDependencySynchronize();

    {
        const float* bs = g_bsum + (b * 8 + warp) * NT;
        float s = (lane < NT) ? bs[lane] : 0.0f;
        #pragma unroll
        for (int o = 16; o > 0; o >>= 1)
            s += __shfl_xor_sync(0xffffffffu, s, o);
        if (lane == 0) sh_invS[warp] = 1.0f / s;
    }
    __syncthreads();

    int hh = t >> 5;
    int dd = D & 127;
    int bh = b * 8 + hh;

    const float* pp = g_partial + bh * (NT * DV) + dd;
    float4 a = make_float4(0.f, 0.f, 0.f, 0.f);
    #pragma unroll
    for (int k = 0; k < NT; k++) {
        float4 x = *(const float4*)(pp + k * DV);
        a.x += x.x; a.y += x.y; a.z += x.z; a.w += x.w;
    }
    float invS = sh_invS[hh];
    a.x *= invS; a.y *= invS; a.z *= invS; a.w *= invS;

    float s = a.x + a.y + a.z + a.w;
    float q = a.x * a.x + a.y * a.y + a.z * a.z + a.w * a.w;
    #pragma unroll
    for (int o = 16; o > 0; o >>= 1) {
        s += __shfl_xor_sync(0xffffffffu, s, o);
        q += __shfl_xor_sync(0xffffffffu, q, o);
    }
    if (lane == 0) { sh_s[warp] = s; sh_q[warp] = q; }
    __syncthreads();
    if (warp == 0 && lane < 8) {
        s = sh_s[lane];
        q = sh_q[lane];
        #pragma unroll
        for (int o = 4; o > 0; o >>= 1) {
            s += __shfl_xor_sync(0x000000ffu, s, o);
            q += __shfl_xor_sync(0x000000ffu, q, o);
        }
        if (lane == 0) { sh_s[0] = s; sh_q[0] = q; }
    }
    __syncthreads();
    float mean = sh_s[0] * (1.0f / EDv);
    float var  = sh_q[0] * (1.0f / EDv) - mean * mean;
    float inv  = rsqrtf(var + 1e-5f);

    float4 o4;
    o4.x = (a.x - mean) * inv * gm.x + bt.x;
    o4.y = (a.y - mean) * inv * gm.y + bt.y;
    o4.z = (a.z - mean) * inv * gm.z + bt.z;
    o4.w = (a.w - mean) * inv * gm.w + bt.w;
    *(float4*)(out + b * EDv + D) = o4;
}

// ---------------------------------------------------------------------------
// Launch
// ---------------------------------------------------------------------------
extern "C" void kernel_launch(void* const* d_in, const int* in_sizes, int n_in,
                              void* d_out, int out_size) {
    const float* keys   = (const float*)d_in[0];
    const float* values = (const float*)d_in[1];
    const float* query  = (const float*)d_in[2];
    const float* k_bias = (const float*)d_in[3];
    const float* v_bias = (const float*)d_in[4];
    const float* sw     = (const float*)d_in[5];
    const float* sb     = (const float*)d_in[6];
    const float* gamma  = (const float*)d_in[7];
    const float* beta   = (const float*)d_in[8];
    float* out = (float*)d_out;

    dim3 g1(NT, BH);
    k_fused<<<g1, 256>>>(keys, k_bias, values, v_bias, query, sw, sb);

    cudaLaunchConfig_t cfg = {};
    cfg.gridDim  = dim3(Bv);
    cfg.blockDim = dim3(256);
    cfg.dynamicSmemBytes = 0;
    cfg.stream = 0;
    cudaLaunchAttribute attrs[1];
    attrs[0].id = cudaLaunchAttributeProgrammaticStreamSerialization;
    attrs[0].val.programmaticStreamSerializationAllowed = 1;
    cfg.attrs = attrs;
    cfg.numAttrs = 1;
    cudaLaunchKernelEx(&cfg, k_ln, gamma, beta, out);
}

// round 15
// speedup vs baseline: 1.1316x; 1.1106x over previous
#include <cuda_runtime.h>
#include <math.h>
#include <float.h>
#include <stdint.h>

// Problem constants
#define Bv   8
#define Lv   4096
#define LP   4097          // L + 1 (bias token)
#define KDv  512
#define EDv  1024
#define DK   64            // KD / H
#define DV   128           // ED / H
#define BH   64            // B * H
#define KCHUNK   (LP * DK)
#define VCHUNK   (LP * DV)
#define KBATCH   (Lv * KDv)
#define VBATCH   (Lv * EDv)
#define NT   8             // j-tiles -> 512 blocks = single wave
#define TILE 513           // ceil(4097 / 8)

// Scratch
__device__ float g_bsum[BH * NT];
__device__ float g_partial[BH * NT * DV];

// ---------------------------------------------------------------------------
// Fused kernel (R12 body, NT=8): for rows j in tile:
//   s_j = dot64(Q[h],K[bh,j,:]); e_j = exp(s_j*w+b); acc += e_j * V[bh,j,:]
// 4 rows/iteration: 2 half-warp K pair loads + 4 front-batched V row loads.
// ---------------------------------------------------------------------------
__global__ void __launch_bounds__(256) k_fused(
        const float* __restrict__ keys,
        const float* __restrict__ k_bias,
        const float* __restrict__ values,
        const float* __restrict__ v_bias,
        const float* __restrict__ query,
        const float* __restrict__ sw,
        const float* __restrict__ sb) {
    __shared__ float4 sq[16];
    __shared__ float4 red[8][32];
    __shared__ float  shs[8];

    int tile = blockIdx.x;
    int bh   = blockIdx.y;
    int b = bh >> 3, h = bh & 7;
    int t    = threadIdx.x;
    int w    = t >> 5;
    int lane = t & 31;
    int half = lane >> 4;
    int li   = lane & 15;
    int c    = lane;

    if (t < 16) sq[t] = *((const float4*)(query + h * DK) + t);
    __syncthreads();

    const float* swh = sw + h * LP;
    const float* sbh = sb + h * LP;
    int kchunk = h * KCHUNK;
    int vchunk = h * VCHUNK;
    const float* kbat = keys   + (size_t)b * KBATCH;
    const float* vbat = values + (size_t)b * VBATCH;

    int j0 = tile * TILE;
    int j1 = min(j0 + TILE, LP);

    float4 acc  = make_float4(0.f, 0.f, 0.f, 0.f);
    float  esum = 0.0f;
    float4 qv   = sq[li];

    int j = j0 + w;
    // main loop: 4 rows (j, j+8, j+16, j+24) per iteration
    for (; j + 24 < j1; j += 32) {
        // --- front-batched K loads: rows (j, j+8) and (j+16, j+24) ---
        int jkA = j + half * 8;
        int jkB = j + 16 + half * 8;
        int fkA = kchunk + jkA * DK + li * 4;
        int fkB = kchunk + jkB * DK + li * 4;
        const float* kpA = (fkA >= KBATCH) ? (k_bias + (fkA - KBATCH)) : (kbat + fkA);
        const float* kpB = (fkB >= KBATCH) ? (k_bias + (fkB - KBATCH)) : (kbat + fkB);
        float4 kvA = __ldcs((const float4*)kpA);
        float4 kvB = __ldcs((const float4*)kpB);

        // --- front-batched V loads: 4 rows ---
        int f0 = vchunk + j * DV;
        int f1 = f0 + 8 * DV, f2 = f0 + 16 * DV, f3 = f0 + 24 * DV;
        const float* r0 = (f0 >= VBATCH) ? (v_bias + (f0 - VBATCH)) : (vbat + f0);
        const float* r1 = (f1 >= VBATCH) ? (v_bias + (f1 - VBATCH)) : (vbat + f1);
        const float* r2 = (f2 >= VBATCH) ? (v_bias + (f2 - VBATCH)) : (vbat + f2);
        const float* r3 = (f3 >= VBATCH) ? (v_bias + (f3 - VBATCH)) : (vbat + f3);
        float4 v0 = __ldcs((const float4*)(r0 + c * 4));
        float4 v1 = __ldcs((const float4*)(r1 + c * 4));
        float4 v2 = __ldcs((const float4*)(r2 + c * 4));
        float4 v3 = __ldcs((const float4*)(r3 + c * 4));

        // --- scores for 4 rows ---
        float sA = kvA.x * qv.x + kvA.y * qv.y + kvA.z * qv.z + kvA.w * qv.w;
        float sB = kvB.x * qv.x + kvB.y * qv.y + kvB.z * qv.z + kvB.w * qv.w;
        #pragma unroll
        for (int o = 8; o > 0; o >>= 1) {
            sA += __shfl_xor_sync(0xffffffffu, sA, o);
            sB += __shfl_xor_sync(0xffffffffu, sB, o);
        }
        float eA2 = expf(sA * __ldg(swh + jkA) + __ldg(sbh + jkA));
        float eB2 = expf(sB * __ldg(swh + jkB) + __ldg(sbh + jkB));
        float e0 = __shfl_sync(0xffffffffu, eA2, 0);
        float e1 = __shfl_sync(0xffffffffu, eA2, 16);
        float e2 = __shfl_sync(0xffffffffu, eB2, 0);
        float e3 = __shfl_sync(0xffffffffu, eB2, 16);

        acc.x += e0 * v0.x + e1 * v1.x + e2 * v2.x + e3 * v3.x;
        acc.y += e0 * v0.y + e1 * v1.y + e2 * v2.y + e3 * v3.y;
        acc.z += e0 * v0.z + e1 * v1.z + e2 * v2.z + e3 * v3.z;
        acc.w += e0 * v0.w + e1 * v1.w + e2 * v2.w + e3 * v3.w;
        if (lane == 0) esum += (e0 + e1) + (e2 + e3);
    }
    // tail: single rows
    for (; j < j1; j += 8) {
        int fk = kchunk + j * DK + li * 4;
        const float* kp = (fk >= KBATCH) ? (k_bias + (fk - KBATCH)) : (kbat + fk);
        float4 kv = __ldcs((const float4*)kp);
        float s = kv.x * qv.x + kv.y * qv.y + kv.z * qv.z + kv.w * qv.w;
        #pragma unroll
        for (int o = 8; o > 0; o >>= 1)
            s += __shfl_xor_sync(0xffffffffu, s, o);
        float e = expf(s * __ldg(swh + j) + __ldg(sbh + j));
        e = __shfl_sync(0xffffffffu, e, 0);

        int fA = vchunk + j * DV;
        const float* rA = (fA >= VBATCH) ? (v_bias + (fA - VBATCH)) : (vbat + fA);
        float4 vA = __ldcs((const float4*)(rA + c * 4));
        acc.x += e * vA.x;
        acc.y += e * vA.y;
        acc.z += e * vA.z;
        acc.w += e * vA.w;
        if (lane == 0) esum += e;
    }

    cudaTriggerProgrammaticLaunchCompletion();

    // cross-warp reduce
    red[w][c] = acc;
    if (lane == 0) shs[w] = esum;
    __syncthreads();
    if (w == 0) {
        float4 a = red[0][c];
        #pragma unroll
        for (int ww = 1; ww < 8; ww++) {
            float4 x = red[ww][c];
            a.x += x.x; a.y += x.y; a.z += x.z; a.w += x.w;
        }
        *(float4*)(g_partial + (bh * NT + tile) * DV + c * 4) = a;
        if (lane == 0) {
            float s = 0.0f;
            #pragma unroll
            for (int ww = 0; ww < 8; ww++) s += shs[ww];
            g_bsum[bh * NT + tile] = s;
        }
    }
}

// ---------------------------------------------------------------------------
// Kernel 2: S[bh] = sum of tile sums; reduce NT partials, /S, LayerNorm.
// PDL secondary.
// ---------------------------------------------------------------------------
__global__ void k_ln(const float* __restrict__ gamma,
                     const float* __restrict__ beta,
                     float* __restrict__ out) {
    __shared__ float sh_invS[8];
    __shared__ float sh_s[8];
    __shared__ float sh_q[8];
    int b = blockIdx.x;
    int t = threadIdx.x;
    int lane = t & 31, warp = t >> 5;

    int D  = t * 4;
    float4 gm = *(const float4*)(gamma + D);
    float4 bt = *(const float4*)(beta + D);

    cudaGridDependencySynchronize();

    {
        const float* bs = g_bsum + (b * 8 + warp) * NT;
        float s = (lane < NT) ? bs[lane] : 0.0f;
        #pragma unroll
        for (int o = 16; o > 0; o >>= 1)
            s += __shfl_xor_sync(0xffffffffu, s, o);
        if (lane == 0) sh_invS[warp] = 1.0f / s;
    }
    __syncthreads();

    int hh = t >> 5;
    int dd = D & 127;
    int bh = b * 8 + hh;

    const float* pp = g_partial + bh * (NT * DV) + dd;
    float4 a = make_float4(0.f, 0.f, 0.f, 0.f);
    #pragma unroll
    for (int k = 0; k < NT; k++) {
        float4 x = *(const float4*)(pp + k * DV);
        a.x += x.x; a.y += x.y; a.z += x.z; a.w += x.w;
    }
    float invS = sh_invS[hh];
    a.x *= invS; a.y *= invS; a.z *= invS; a.w *= invS;

    float s = a.x + a.y + a.z + a.w;
    float q = a.x * a.x + a.y * a.y + a.z * a.z + a.w * a.w;
    #pragma unroll
    for (int o = 16; o > 0; o >>= 1) {
        s += __shfl_xor_sync(0xffffffffu, s, o);
        q += __shfl_xor_sync(0xffffffffu, q, o);
    }
    if (lane == 0) { sh_s[warp] = s; sh_q[warp] = q; }
    __syncthreads();
    if (warp == 0 && lane < 8) {
        s = sh_s[lane];
        q = sh_q[lane];
        #pragma unroll
        for (int o = 4; o > 0; o >>= 1) {
            s += __shfl_xor_sync(0x000000ffu, s, o);
            q += __shfl_xor_sync(0x000000ffu, q, o);
        }
        if (lane == 0) { sh_s[0] = s; sh_q[0] = q; }
    }
    __syncthreads();
    float mean = sh_s[0] * (1.0f / EDv);
    float var  = sh_q[0] * (1.0f / EDv) - mean * mean;
    float inv  = rsqrtf(var + 1e-5f);

    float4 o4;
    o4.x = (a.x - mean) * inv * gm.x + bt.x;
    o4.y = (a.y - mean) * inv * gm.y + bt.y;
    o4.z = (a.z - mean) * inv * gm.z + bt.z;
    o4.w = (a.w - mean) * inv * gm.w + bt.w;
    *(float4*)(out + b * EDv + D) = o4;
}

// ---------------------------------------------------------------------------
// Launch
// ---------------------------------------------------------------------------
extern "C" void kernel_launch(void* const* d_in, const int* in_sizes, int n_in,
                              void* d_out, int out_size) {
    const float* keys   = (const float*)d_in[0];
    const float* values = (const float*)d_in[1];
    const float* query  = (const float*)d_in[2];
    const float* k_bias = (const float*)d_in[3];
    const float* v_bias = (const float*)d_in[4];
    const float* sw     = (const float*)d_in[5];
    const float* sb     = (const float*)d_in[6];
    const float* gamma  = (const float*)d_in[7];
    const float* beta   = (const float*)d_in[8];
    float* out = (float*)d_out;

    dim3 g1(NT, BH);
    k_fused<<<g1, 256>>>(keys, k_bias, values, v_bias, query, sw, sb);

    cudaLaunchConfig_t cfg = {};
    cfg.gridDim  = dim3(Bv);
    cfg.blockDim = dim3(256);
    cfg.dynamicSmemBytes = 0;
    cfg.stream = 0;
    cudaLaunchAttribute attrs[1];
    attrs[0].id = cudaLaunchAttributeProgrammaticStreamSerialization;
    attrs[0].val.programmaticStreamSerializationAllowed = 1;
    cfg.attrs = attrs;
    cfg.numAttrs = 1;
    cudaLaunchKernelEx(&cfg, k_ln, gamma, beta, out);
}

// round 16
// speedup vs baseline: 1.1380x; 1.0057x over previous
#include <cuda_runtime.h>
#include <math.h>
#include <float.h>
#include <stdint.h>

// Problem constants
#define Bv   8
#define Lv   4096
#define LP   4097          // L + 1 (bias token)
#define KDv  512
#define EDv  1024
#define DK   64            // KD / H
#define DV   128           // ED / H
#define BH   64            // B * H
#define KCHUNK   (LP * DK)
#define VCHUNK   (LP * DV)
#define KBATCH   (Lv * KDv)
#define VBATCH   (Lv * EDv)
#define NT   8             // j-tiles -> 512 blocks = single wave
#define TILE 513           // ceil(4097 / 8)

// Scratch
__device__ float g_bsum[BH * NT];
__device__ float g_partial[BH * NT * DV];

// ---------------------------------------------------------------------------
// Mainloop body, templated on SAFE (no bias-region selects, uniform bases).
// ---------------------------------------------------------------------------
template <bool SAFE>
__device__ __forceinline__ void mainloop(
        int& j, int j1,
        const float* __restrict__ kbase,   // SAFE: kbat+kchunk  else kbat
        const float* __restrict__ vbase,   // SAFE: vbat+vchunk  else vbat
        const float* __restrict__ k_bias,
        const float* __restrict__ v_bias,
        int kchunk, int vchunk,
        const float* __restrict__ swh, const float* __restrict__ sbh,
        float4 qv, int half, int li, int c, int lane,
        float4& acc, float& esum) {
    for (; j + 24 < j1; j += 32) {
        int jkA = j + half * 8;
        int jkB = j + 16 + half * 8;

        const float *kpA, *kpB, *r0, *r1, *r2, *r3;
        if (SAFE) {
            kpA = kbase + jkA * DK + li * 4;
            kpB = kbase + jkB * DK + li * 4;
            const float* vb = vbase + j * DV + c * 4;
            r0 = vb;             r1 = vb + 8 * DV;
            r2 = vb + 16 * DV;   r3 = vb + 24 * DV;
        } else {
            int fkA = kchunk + jkA * DK + li * 4;
            int fkB = kchunk + jkB * DK + li * 4;
            kpA = (fkA >= KBATCH) ? (k_bias + (fkA - KBATCH)) : (kbase + fkA);
            kpB = (fkB >= KBATCH) ? (k_bias + (fkB - KBATCH)) : (kbase + fkB);
            int f0 = vchunk + j * DV;
            int f1 = f0 + 8 * DV, f2 = f0 + 16 * DV, f3 = f0 + 24 * DV;
            r0 = ((f0 >= VBATCH) ? (v_bias + (f0 - VBATCH)) : (vbase + f0)) + c * 4;
            r1 = ((f1 >= VBATCH) ? (v_bias + (f1 - VBATCH)) : (vbase + f1)) + c * 4;
            r2 = ((f2 >= VBATCH) ? (v_bias + (f2 - VBATCH)) : (vbase + f2)) + c * 4;
            r3 = ((f3 >= VBATCH) ? (v_bias + (f3 - VBATCH)) : (vbase + f3)) + c * 4;
        }

        float4 kvA = __ldcs((const float4*)kpA);
        float4 kvB = __ldcs((const float4*)kpB);
        float4 v0  = __ldcs((const float4*)r0);
        float4 v1  = __ldcs((const float4*)r1);
        float4 v2  = __ldcs((const float4*)r2);
        float4 v3  = __ldcs((const float4*)r3);

        float sA = kvA.x * qv.x + kvA.y * qv.y + kvA.z * qv.z + kvA.w * qv.w;
        float sB = kvB.x * qv.x + kvB.y * qv.y + kvB.z * qv.z + kvB.w * qv.w;
        #pragma unroll
        for (int o = 8; o > 0; o >>= 1) {
            sA += __shfl_xor_sync(0xffffffffu, sA, o);
            sB += __shfl_xor_sync(0xffffffffu, sB, o);
        }
        float eA2 = expf(sA * __ldg(swh + jkA) + __ldg(sbh + jkA));
        float eB2 = expf(sB * __ldg(swh + jkB) + __ldg(sbh + jkB));
        float e0 = __shfl_sync(0xffffffffu, eA2, 0);
        float e1 = __shfl_sync(0xffffffffu, eA2, 16);
        float e2 = __shfl_sync(0xffffffffu, eB2, 0);
        float e3 = __shfl_sync(0xffffffffu, eB2, 16);

        acc.x += e0 * v0.x + e1 * v1.x + e2 * v2.x + e3 * v3.x;
        acc.y += e0 * v0.y + e1 * v1.y + e2 * v2.y + e3 * v3.y;
        acc.z += e0 * v0.z + e1 * v1.z + e2 * v2.z + e3 * v3.z;
        acc.w += e0 * v0.w + e1 * v1.w + e2 * v2.w + e3 * v3.w;
        if (lane == 0) esum += (e0 + e1) + (e2 + e3);
    }
}

// ---------------------------------------------------------------------------
// Fused kernel (R15 structure + safe/generic split).
// ---------------------------------------------------------------------------
__global__ void __launch_bounds__(256) k_fused(
        const float* __restrict__ keys,
        const float* __restrict__ k_bias,
        const float* __restrict__ values,
        const float* __restrict__ v_bias,
        const float* __restrict__ query,
        const float* __restrict__ sw,
        const float* __restrict__ sb) {
    __shared__ float4 sq[16];
    __shared__ float4 red[8][32];
    __shared__ float  shs[8];

    int tile = blockIdx.x;
    int bh   = blockIdx.y;
    int b = bh >> 3, h = bh & 7;
    int t    = threadIdx.x;
    int w    = t >> 5;
    int lane = t & 31;
    int half = lane >> 4;
    int li   = lane & 15;
    int c    = lane;

    if (t < 16) sq[t] = *((const float4*)(query + h * DK) + t);
    __syncthreads();

    const float* swh = sw + h * LP;
    const float* sbh = sb + h * LP;
    int kchunk = h * KCHUNK;
    int vchunk = h * VCHUNK;
    const float* kbat = keys   + (size_t)b * KBATCH;
    const float* vbat = values + (size_t)b * VBATCH;

    int j0 = tile * TILE;
    int j1 = min(j0 + TILE, LP);

    float4 acc  = make_float4(0.f, 0.f, 0.f, 0.f);
    float  esum = 0.0f;
    float4 qv   = sq[li];

    // Whole j-range within real K and V data? (only h==7, last tile fails)
    bool safe = (kchunk + (j1 - 1) * DK + DK <= KBATCH) &&
                (vchunk + (j1 - 1) * DV + DV <= VBATCH);

    int j = j0 + w;
    if (safe) {
        mainloop<true>(j, j1, kbat + kchunk, vbat + vchunk, k_bias, v_bias,
                       kchunk, vchunk, swh, sbh, qv, half, li, c, lane,
                       acc, esum);
    } else {
        mainloop<false>(j, j1, kbat, vbat, k_bias, v_bias,
                        kchunk, vchunk, swh, sbh, qv, half, li, c, lane,
                        acc, esum);
    }
    // tail: single rows (generic addressing)
    for (; j < j1; j += 8) {
        int fk = kchunk + j * DK + li * 4;
        const float* kp = (fk >= KBATCH) ? (k_bias + (fk - KBATCH)) : (kbat + fk);
        float4 kv = __ldcs((const float4*)kp);
        float s = kv.x * qv.x + kv.y * qv.y + kv.z * qv.z + kv.w * qv.w;
        #pragma unroll
        for (int o = 8; o > 0; o >>= 1)
            s += __shfl_xor_sync(0xffffffffu, s, o);
        float e = expf(s * __ldg(swh + j) + __ldg(sbh + j));
        e = __shfl_sync(0xffffffffu, e, 0);

        int fA = vchunk + j * DV;
        const float* rA = (fA >= VBATCH) ? (v_bias + (fA - VBATCH)) : (vbat + fA);
        float4 vA = __ldcs((const float4*)(rA + c * 4));
        acc.x += e * vA.x;
        acc.y += e * vA.y;
        acc.z += e * vA.z;
        acc.w += e * vA.w;
        if (lane == 0) esum += e;
    }

    cudaTriggerProgrammaticLaunchCompletion();

    // cross-warp reduce
    red[w][c] = acc;
    if (lane == 0) shs[w] = esum;
    __syncthreads();
    if (w == 0) {
        float4 a = red[0][c];
        #pragma unroll
        for (int ww = 1; ww < 8; ww++) {
            float4 x = red[ww][c];
            a.x += x.x; a.y += x.y; a.z += x.z; a.w += x.w;
        }
        *(float4*)(g_partial + (bh * NT + tile) * DV + c * 4) = a;
        if (lane == 0) {
            float s = 0.0f;
            #pragma unroll
            for (int ww = 0; ww < 8; ww++) s += shs[ww];
            g_bsum[bh * NT + tile] = s;
        }
    }
}

// ---------------------------------------------------------------------------
// Kernel 2: S[bh] = sum of tile sums; reduce NT partials, /S, LayerNorm.
// PDL secondary.
// ---------------------------------------------------------------------------
__global__ void k_ln(const float* __restrict__ gamma,
                     const float* __restrict__ beta,
                     float* __restrict__ out) {
    __shared__ float sh_invS[8];
    __shared__ float sh_s[8];
    __shared__ float sh_q[8];
    int b = blockIdx.x;
    int t = threadIdx.x;
    int lane = t & 31, warp = t >> 5;

    int D  = t * 4;
    float4 gm = *(const float4*)(gamma + D);
    float4 bt = *(const float4*)(beta + D);

    cudaGridDependencySynchronize();

    {
        const float* bs = g_bsum + (b * 8 + warp) * NT;
        float s = (lane < NT) ? bs[lane] : 0.0f;
        #pragma unroll
        for (int o = 16; o > 0; o >>= 1)
            s += __shfl_xor_sync(0xffffffffu, s, o);
        if (lane == 0) sh_invS[warp] = 1.0f / s;
    }
    __syncthreads();

    int hh = t >> 5;
    int dd = D & 127;
    int bh = b * 8 + hh;

    const float* pp = g_partial + bh * (NT * DV) + dd;
    float4 a = make_float4(0.f, 0.f, 0.f, 0.f);
    #pragma unroll
    for (int k = 0; k < NT; k++) {
        float4 x = *(const float4*)(pp + k * DV);
        a.x += x.x; a.y += x.y; a.z += x.z; a.w += x.w;
    }
    float invS = sh_invS[hh];
    a.x *= invS; a.y *= invS; a.z *= invS; a.w *= invS;

    float s = a.x + a.y + a.z + a.w;
    float q = a.x * a.x + a.y * a.y + a.z * a.z + a.w * a.w;
    #pragma unroll
    for (int o = 16; o > 0; o >>= 1) {
        s += __shfl_xor_sync(0xffffffffu, s, o);
        q += __shfl_xor_sync(0xffffffffu, q, o);
    }
    if (lane == 0) { sh_s[warp] = s; sh_q[warp] = q; }
    __syncthreads();
    if (warp == 0 && lane < 8) {
        s = sh_s[lane];
        q = sh_q[lane];
        #pragma unroll
        for (int o = 4; o > 0; o >>= 1) {
            s += __shfl_xor_sync(0x000000ffu, s, o);
            q += __shfl_xor_sync(0x000000ffu, q, o);
        }
        if (lane == 0) { sh_s[0] = s; sh_q[0] = q; }
    }
    __syncthreads();
    float mean = sh_s[0] * (1.0f / EDv);
    float var  = sh_q[0] * (1.0f / EDv) - mean * mean;
    float inv  = rsqrtf(var + 1e-5f);

    float4 o4;
    o4.x = (a.x - mean) * inv * gm.x + bt.x;
    o4.y = (a.y - mean) * inv * gm.y + bt.y;
    o4.z = (a.z - mean) * inv * gm.z + bt.z;
    o4.w = (a.w - mean) * inv * gm.w + bt.w;
    *(float4*)(out + b * EDv + D) = o4;
}

// ---------------------------------------------------------------------------
// Launch
// ---------------------------------------------------------------------------
extern "C" void kernel_launch(void* const* d_in, const int* in_sizes, int n_in,
                              void* d_out, int out_size) {
    const float* keys   = (const float*)d_in[0];
    const float* values = (const float*)d_in[1];
    const float* query  = (const float*)d_in[2];
    const float* k_bias = (const float*)d_in[3];
    const float* v_bias = (const float*)d_in[4];
    const float* sw     = (const float*)d_in[5];
    const float* sb     = (const float*)d_in[6];
    const float* gamma  = (const float*)d_in[7];
    const float* beta   = (const float*)d_in[8];
    float* out = (float*)d_out;

    dim3 g1(NT, BH);
    k_fused<<<g1, 256>>>(keys, k_bias, values, v_bias, query, sw, sb);

    cudaLaunchConfig_t cfg = {};
    cfg.gridDim  = dim3(Bv);
    cfg.blockDim = dim3(256);
    cfg.dynamicSmemBytes = 0;
    cfg.stream = 0;
    cudaLaunchAttribute attrs[1];
    attrs[0].id = cudaLaunchAttributeProgrammaticStreamSerialization;
    attrs[0].val.programmaticStreamSerializationAllowed = 1;
    cfg.attrs = attrs;
    cfg.numAttrs = 1;
    cudaLaunchKernelEx(&cfg, k_ln, gamma, beta, out);
}